// round 1
// baseline (speedup 1.0000x reference)
#include <cuda_runtime.h>
#include <cstdint>

#define N_NODES 8192
#define F_IN    1024
#define F_OUT   512

// ---------------- device scratch (no allocations allowed) ----------------
__device__ float g_S[N_NODES * F_OUT];   // seq_fts, fp32 (16 MB)
__device__ float g_f1[N_NODES];
__device__ float g_f2[N_NODES];
__device__ float g_Z[N_NODES];

// ---------------- helpers ----------------
// Polynomial exp on the FMA pipe (avoids MUFU.EX2 throughput wall: 67M exps
// via MUFU would cost ~480us; this costs ~15us). |rel err| ~ 1e-7.
__device__ __forceinline__ float fast_exp(float x) {
    float t = x * 1.4426950408889634f;          // x * log2(e)
    t = fminf(fmaxf(t, -126.0f), 126.0f);
    float fi = rintf(t);
    float f  = t - fi;                           // [-0.5, 0.5]
    float p  =          1.5403530393381609e-4f;  // (ln2)^6/6!
    p = fmaf(p, f, 1.3333558146428443e-3f);
    p = fmaf(p, f, 9.6181291076284772e-3f);
    p = fmaf(p, f, 5.5504108664821580e-2f);
    p = fmaf(p, f, 2.4022650695910071e-1f);
    p = fmaf(p, f, 6.9314718055994531e-1f);
    p = fmaf(p, f, 1.0f);
    int e = (int)fi;
    return p * __int_as_float((e + 127) << 23);
}

__device__ __forceinline__ unsigned tf32_of(float x) {
    unsigned r;
    asm("cvt.rna.tf32.f32 %0, %1;" : "=r"(r) : "f"(x));
    return r;
}

__device__ __forceinline__ void mma_tf32(float* d, const unsigned* a, const unsigned* b) {
    asm volatile(
        "mma.sync.aligned.m16n8k8.row.col.f32.tf32.tf32.f32 "
        "{%0,%1,%2,%3}, {%4,%5,%6,%7}, {%8,%9}, {%0,%1,%2,%3};"
        : "+f"(d[0]), "+f"(d[1]), "+f"(d[2]), "+f"(d[3])
        : "r"(a[0]), "r"(a[1]), "r"(a[2]), "r"(a[3]), "r"(b[0]), "r"(b[1]));
}

// ---------------- K1: seq_fts = x @ seq_W.T  (3xTF32 split => ~fp32 exact) ----
// A = x [8192,1024] row-major (M,K); B = seq_W [512,1024] row-major = (N,K).
// BM=128 BN=64 BK=32, 256 thr = 8 warps (4M x 2N), warp tile 32x32.
__global__ __launch_bounds__(256) void k1_seqfts(const float* __restrict__ X,
                                                 const float* __restrict__ W) {
    __shared__ float As[128][36];   // pad 36: 4*grp+tig banks -> conflict-free frags
    __shared__ float Bs[64][36];
    const int tid = threadIdx.x;
    const int m0 = blockIdx.y * 128;
    const int n0 = blockIdx.x * 64;
    const int warp = tid >> 5, lane = tid & 31;
    const int grp = lane >> 2, tig = lane & 3;
    const int wm = warp & 3, wn = warp >> 2;
    const int lr = tid >> 3;
    const int lc = (tid & 7) << 2;

    float d[2][4][4];
#pragma unroll
    for (int i = 0; i < 2; i++)
#pragma unroll
        for (int j = 0; j < 4; j++)
#pragma unroll
            for (int q = 0; q < 4; q++) d[i][j][q] = 0.0f;

    for (int k0 = 0; k0 < F_IN; k0 += 32) {
#pragma unroll
        for (int p = 0; p < 4; p++) {
            float4 v = *(const float4*)&X[(size_t)(m0 + lr + p * 32) * F_IN + k0 + lc];
            *(float4*)&As[lr + p * 32][lc] = v;
        }
#pragma unroll
        for (int p = 0; p < 2; p++) {
            float4 v = *(const float4*)&W[(size_t)(n0 + lr + p * 32) * F_IN + k0 + lc];
            *(float4*)&Bs[lr + p * 32][lc] = v;
        }
        __syncthreads();
#pragma unroll
        for (int kk = 0; kk < 32; kk += 8) {
            unsigned ah[2][4], al[2][4];
#pragma unroll
            for (int mt = 0; mt < 2; mt++) {
                int rb = wm * 32 + mt * 16;
                float av[4];
                av[0] = As[rb + grp][kk + tig];
                av[1] = As[rb + grp + 8][kk + tig];
                av[2] = As[rb + grp][kk + tig + 4];
                av[3] = As[rb + grp + 8][kk + tig + 4];
#pragma unroll
                for (int q = 0; q < 4; q++) {
                    unsigned h = tf32_of(av[q]);
                    ah[mt][q] = h;
                    al[mt][q] = tf32_of(av[q] - __uint_as_float(h));
                }
            }
            unsigned bh[4][2], bl[4][2];
#pragma unroll
            for (int nt = 0; nt < 4; nt++) {
                int cb = wn * 32 + nt * 8;
                float bv[2];
                bv[0] = Bs[cb + grp][kk + tig];
                bv[1] = Bs[cb + grp][kk + tig + 4];
#pragma unroll
                for (int q = 0; q < 2; q++) {
                    unsigned h = tf32_of(bv[q]);
                    bh[nt][q] = h;
                    bl[nt][q] = tf32_of(bv[q] - __uint_as_float(h));
                }
            }
#pragma unroll
            for (int mt = 0; mt < 2; mt++)
#pragma unroll
                for (int nt = 0; nt < 4; nt++) {
                    mma_tf32(d[mt][nt], ah[mt], bh[nt]);
                    mma_tf32(d[mt][nt], al[mt], bh[nt]);
                    mma_tf32(d[mt][nt], ah[mt], bl[nt]);
                }
        }
        __syncthreads();
    }
#pragma unroll
    for (int mt = 0; mt < 2; mt++)
#pragma unroll
        for (int nt = 0; nt < 4; nt++) {
            int r = m0 + wm * 32 + mt * 16 + grp;
            int c = n0 + wn * 32 + nt * 8 + tig * 2;
            g_S[(size_t)r * F_OUT + c]           = d[mt][nt][0];
            g_S[(size_t)r * F_OUT + c + 1]       = d[mt][nt][1];
            g_S[(size_t)(r + 8) * F_OUT + c]     = d[mt][nt][2];
            g_S[(size_t)(r + 8) * F_OUT + c + 1] = d[mt][nt][3];
        }
}

// ---------------- K2: f1 = S@f1_w + b1, f2 = S@f2_w + b2 (one warp / row) ----
__global__ __launch_bounds__(256) void k2_fvec(const float* __restrict__ f1w,
                                               const float* __restrict__ f1b,
                                               const float* __restrict__ f2w,
                                               const float* __restrict__ f2b) {
    int row = blockIdx.x * 8 + (threadIdx.x >> 5);
    int lane = threadIdx.x & 31;
    const float* Sr = g_S + (size_t)row * F_OUT;
    float s1 = 0.f, s2 = 0.f;
    for (int c = lane; c < F_OUT; c += 32) {
        float v = Sr[c];
        s1 = fmaf(v, f1w[c], s1);
        s2 = fmaf(v, f2w[c], s2);
    }
#pragma unroll
    for (int o = 16; o > 0; o >>= 1) {
        s1 += __shfl_xor_sync(0xffffffff, s1, o);
        s2 += __shfl_xor_sync(0xffffffff, s2, o);
    }
    if (lane == 0) {
        g_f1[row] = s1 + f1b[0];
        g_f2[row] = s2 + f2b[0];
    }
}

// ---------------- K3: per-row Z = sum_j exp(pre_ij)  +  RWR counts ----------
// No max subtraction needed: pre in ~[-10,16], exp fits fp32 with full margin.
__global__ __launch_bounds__(256) void k3_z_rwr(const float* __restrict__ adj,
                                                const int* __restrict__ adj_ad,
                                                float* __restrict__ out_ri,
                                                int write_ri) {
    const int i = blockIdx.x;
    const int tid = threadIdx.x;
    const float f1i = g_f1[i];
    const float4* arow = (const float4*)(adj + (size_t)i * N_NODES);
    const int4*   crow = (const int4*)(adj_ad + (size_t)i * N_NODES);
    float z = 0.0f;
    int cnt = 0;
    for (int j4 = tid; j4 < N_NODES / 4; j4 += 256) {
        float4 a = arow[j4];
        int4 c = crow[j4];
        float4 f2v = *(const float4*)&g_f2[j4 * 4];
        float l;
        l = f1i + f2v.x; l = l > 0.f ? l : 0.2f * l; z += fast_exp(l + a.x);
        l = f1i + f2v.y; l = l > 0.f ? l : 0.2f * l; z += fast_exp(l + a.y);
        l = f1i + f2v.z; l = l > 0.f ? l : 0.2f * l; z += fast_exp(l + a.z);
        l = f1i + f2v.w; l = l > 0.f ? l : 0.2f * l; z += fast_exp(l + a.w);
        cnt += (c.x == 2 || c.x == 3);
        cnt += (c.y == 2 || c.y == 3);
        cnt += (c.z == 2 || c.z == 3);
        cnt += (c.w == 2 || c.w == 3);
    }
    __shared__ float sz[256];
    __shared__ int   sc[256];
    sz[tid] = z; sc[tid] = cnt;
    __syncthreads();
    for (int s = 128; s > 0; s >>= 1) {
        if (tid < s) { sz[tid] += sz[tid + s]; sc[tid] += sc[tid + s]; }
        __syncthreads();
    }
    if (tid == 0) {
        g_Z[i] = sz[0];
        if (write_ri) {
            float k = (float)sc[0];
            float den = 1.0f - 0.25f * k;
            float r0, rn;
            if (den == 0.0f) { r0 = 1.0f; rn = 0.5f; }
            else             { r0 = fabsf(1.0f / den); rn = fabsf(0.5f / den); }
            out_ri[2 * i]     = r0;
            out_ri[2 * i + 1] = rn;
        }
    }
}

// ---------------- K4: fused attention GEMM  h = elu(P@S / Z + bias) --------
// P tile generated on the fly from adj + f1 + f2 (flash-style, never
// materialized). tf32 MMA. BM=128 BN=256 BK=32, 256 thr = 8 warps (2M x 4N),
// warp tile 64x64 -> 32 m16n8 tiles, 128 accum regs.
#define K4_PPAD 36
#define K4_BPAD 260
#define K4_SMEM (128 * K4_PPAD * 4 + 32 * K4_BPAD * 4 + 256 * 4)

__global__ __launch_bounds__(256, 1) void k4_attn(const float* __restrict__ adj,
                                                  const float* __restrict__ bias,
                                                  float* __restrict__ out) {
    extern __shared__ unsigned char smem_raw[];
    unsigned* Ps = (unsigned*)smem_raw;                              // [128][36] tf32
    unsigned* Bs = (unsigned*)(smem_raw + 128 * K4_PPAD * 4);        // [32][260] tf32
    float* f1s = (float*)(smem_raw + 128 * K4_PPAD * 4 + 32 * K4_BPAD * 4); // [128]
    float* rzs = f1s + 128;                                          // [128]

    const int tid = threadIdx.x;
    const int m0 = blockIdx.y * 128;
    const int n0 = blockIdx.x * 256;
    const int warp = tid >> 5, lane = tid & 31;
    const int grp = lane >> 2, tig = lane & 3;
    const int wm = warp >> 2, wn = warp & 3;

    if (tid < 128) {
        f1s[tid] = g_f1[m0 + tid];
        rzs[tid] = 1.0f / g_Z[m0 + tid];
    }

    float d[4][8][4];
#pragma unroll
    for (int mt = 0; mt < 4; mt++)
#pragma unroll
        for (int nt = 0; nt < 8; nt++)
#pragma unroll
            for (int q = 0; q < 4; q++) d[mt][nt][q] = 0.0f;

    const int gr = tid >> 3;         // 0..31 (row slice for P gen)
    const int gc = (tid & 7) << 2;   // 0..28 (col slice for P gen)

    __syncthreads();

    for (int j0 = 0; j0 < N_NODES; j0 += 32) {
        // --- generate P tile: p = exp(leakyrelu(f1_i + f2_j) + adj_ij) ---
        float4 f2v = *(const float4*)&g_f2[j0 + gc];
#pragma unroll
        for (int p = 0; p < 4; p++) {
            int r = gr + p * 32;
            float4 a = *(const float4*)&adj[(size_t)(m0 + r) * N_NODES + j0 + gc];
            float f1v = f1s[r];
            float l, e0, e1, e2, e3;
            l = f1v + f2v.x; l = l > 0.f ? l : 0.2f * l; e0 = fast_exp(l + a.x);
            l = f1v + f2v.y; l = l > 0.f ? l : 0.2f * l; e1 = fast_exp(l + a.y);
            l = f1v + f2v.z; l = l > 0.f ? l : 0.2f * l; e2 = fast_exp(l + a.z);
            l = f1v + f2v.w; l = l > 0.f ? l : 0.2f * l; e3 = fast_exp(l + a.w);
            uint4 q;
            q.x = tf32_of(e0); q.y = tf32_of(e1); q.z = tf32_of(e2); q.w = tf32_of(e3);
            *(uint4*)&Ps[r * K4_PPAD + gc] = q;
        }
        // --- stage S tile [32 x 256] as tf32 ---
#pragma unroll
        for (int p = 0; p < 8; p++) {
            int idx = p * 256 + tid;
            int r = idx >> 6;
            int c = (idx & 63) << 2;
            float4 v = *(const float4*)&g_S[(size_t)(j0 + r) * F_OUT + n0 + c];
            uint4 q;
            q.x = tf32_of(v.x); q.y = tf32_of(v.y); q.z = tf32_of(v.z); q.w = tf32_of(v.w);
            *(uint4*)&Bs[r * K4_BPAD + c] = q;
        }
        __syncthreads();
        // --- MMA over this K-slab ---
#pragma unroll
        for (int kk = 0; kk < 32; kk += 8) {
            unsigned a[4][4];
#pragma unroll
            for (int mt = 0; mt < 4; mt++) {
                int rb = wm * 64 + mt * 16;
                a[mt][0] = Ps[(rb + grp) * K4_PPAD + kk + tig];
                a[mt][1] = Ps[(rb + grp + 8) * K4_PPAD + kk + tig];
                a[mt][2] = Ps[(rb + grp) * K4_PPAD + kk + tig + 4];
                a[mt][3] = Ps[(rb + grp + 8) * K4_PPAD + kk + tig + 4];
            }
            unsigned b[8][2];
#pragma unroll
            for (int nt = 0; nt < 8; nt++) {
                int cb = wn * 64 + nt * 8;
                b[nt][0] = Bs[(kk + tig) * K4_BPAD + cb + grp];
                b[nt][1] = Bs[(kk + tig + 4) * K4_BPAD + cb + grp];
            }
#pragma unroll
            for (int mt = 0; mt < 4; mt++)
#pragma unroll
                for (int nt = 0; nt < 8; nt++)
                    mma_tf32(d[mt][nt], a[mt], b[nt]);
        }
        __syncthreads();
    }

    // --- epilogue: /Z, +bias, ELU ---
#pragma unroll
    for (int mt = 0; mt < 4; mt++) {
        int rl = wm * 64 + mt * 16 + grp;
        float rz0 = rzs[rl], rz1 = rzs[rl + 8];
        int gi = m0 + rl;
#pragma unroll
        for (int nt = 0; nt < 8; nt++) {
            int cl = wn * 64 + nt * 8 + tig * 2;
            int gf = n0 + cl;
            float b0 = bias[gf], b1 = bias[gf + 1];
            float v;
            v = fmaf(d[mt][nt][0], rz0, b0);
            out[(size_t)gi * F_OUT + gf]           = v > 0.f ? v : fast_exp(v) - 1.0f;
            v = fmaf(d[mt][nt][1], rz0, b1);
            out[(size_t)gi * F_OUT + gf + 1]       = v > 0.f ? v : fast_exp(v) - 1.0f;
            v = fmaf(d[mt][nt][2], rz1, b0);
            out[(size_t)(gi + 8) * F_OUT + gf]     = v > 0.f ? v : fast_exp(v) - 1.0f;
            v = fmaf(d[mt][nt][3], rz1, b1);
            out[(size_t)(gi + 8) * F_OUT + gf + 1] = v > 0.f ? v : fast_exp(v) - 1.0f;
        }
    }
}

// ---------------- launch ----------------
extern "C" void kernel_launch(void* const* d_in, const int* in_sizes, int n_in,
                              void* d_out, int out_size) {
    const float* x      = (const float*)d_in[0];
    const float* adj    = (const float*)d_in[1];
    const int*   adj_ad = (const int*)d_in[2];
    const float* seq_W  = (const float*)d_in[3];
    const float* f1w    = (const float*)d_in[4];
    const float* f1b    = (const float*)d_in[5];
    const float* f2w    = (const float*)d_in[6];
    const float* f2b    = (const float*)d_in[7];
    const float* bias   = (const float*)d_in[8];
    float* out = (float*)d_out;

    cudaFuncSetAttribute(k4_attn, cudaFuncAttributeMaxDynamicSharedMemorySize, K4_SMEM);

    k1_seqfts<<<dim3(8, 64), 256>>>(x, seq_W);
    k2_fvec<<<N_NODES / 8, 256>>>(f1w, f1b, f2w, f2b);
    int write_ri = (out_size >= N_NODES * F_OUT + 2 * N_NODES) ? 1 : 0;
    k3_z_rwr<<<N_NODES, 256>>>(adj, adj_ad, out + (size_t)N_NODES * F_OUT, write_ri);
    k4_attn<<<dim3(2, 64), 256, K4_SMEM>>>(adj, bias, out);
}

// round 2
// speedup vs baseline: 1.1994x; 1.1994x over previous
#include <cuda_runtime.h>
#include <cstdint>

#define N_NODES 8192
#define F_IN    1024
#define F_OUT   512

// ---------------- device scratch (no allocations allowed) ----------------
__device__ float    g_S [N_NODES * F_OUT];   // seq_fts fp32 (16 MB) - for k2
__device__ unsigned g_St[N_NODES * F_OUT];   // seq_fts tf32 bits (16 MB) - for k4 cp.async
__device__ float    g_f1[N_NODES];
__device__ float    g_f2[N_NODES];

// ---------------- helpers ----------------
// Polynomial exp on the FMA pipe (avoids the MUFU.EX2 throughput wall).
__device__ __forceinline__ float fast_exp(float x) {
    float t = x * 1.4426950408889634f;
    t = fminf(fmaxf(t, -126.0f), 126.0f);
    float fi = rintf(t);
    float f  = t - fi;
    float p  =          1.5403530393381609e-4f;
    p = fmaf(p, f, 1.3333558146428443e-3f);
    p = fmaf(p, f, 9.6181291076284772e-3f);
    p = fmaf(p, f, 5.5504108664821580e-2f);
    p = fmaf(p, f, 2.4022650695910071e-1f);
    p = fmaf(p, f, 6.9314718055994531e-1f);
    p = fmaf(p, f, 1.0f);
    int e = (int)fi;
    return p * __int_as_float((e + 127) << 23);
}

__device__ __forceinline__ unsigned tf32_of(float x) {
    unsigned r;
    asm("cvt.rna.tf32.f32 %0, %1;" : "=r"(r) : "f"(x));
    return r;
}

__device__ __forceinline__ void mma_tf32(float* d, const unsigned* a, const unsigned* b) {
    asm volatile(
        "mma.sync.aligned.m16n8k8.row.col.f32.tf32.tf32.f32 "
        "{%0,%1,%2,%3}, {%4,%5,%6,%7}, {%8,%9}, {%0,%1,%2,%3};"
        : "+f"(d[0]), "+f"(d[1]), "+f"(d[2]), "+f"(d[3])
        : "r"(a[0]), "r"(a[1]), "r"(a[2]), "r"(a[3]), "r"(b[0]), "r"(b[1]));
}

__device__ __forceinline__ void cp16(void* smem_ptr, const void* gptr) {
    unsigned sa = (unsigned)__cvta_generic_to_shared(smem_ptr);
    asm volatile("cp.async.cg.shared.global [%0], [%1], 16;" :: "r"(sa), "l"(gptr));
}
__device__ __forceinline__ void cp_commit() {
    asm volatile("cp.async.commit_group;");
}
__device__ __forceinline__ void cp_wait1() {
    asm volatile("cp.async.wait_group 1;");
}

// ---------------- K1: seq_fts = x @ seq_W.T  (3xTF32 split => ~fp32 exact) ----
__global__ __launch_bounds__(256) void k1_seqfts(const float* __restrict__ X,
                                                 const float* __restrict__ W) {
    __shared__ float As[128][36];
    __shared__ float Bs[64][36];
    const int tid = threadIdx.x;
    const int m0 = blockIdx.y * 128;
    const int n0 = blockIdx.x * 64;
    const int warp = tid >> 5, lane = tid & 31;
    const int grp = lane >> 2, tig = lane & 3;
    const int wm = warp & 3, wn = warp >> 2;
    const int lr = tid >> 3;
    const int lc = (tid & 7) << 2;

    float d[2][4][4];
#pragma unroll
    for (int i = 0; i < 2; i++)
#pragma unroll
        for (int j = 0; j < 4; j++)
#pragma unroll
            for (int q = 0; q < 4; q++) d[i][j][q] = 0.0f;

    for (int k0 = 0; k0 < F_IN; k0 += 32) {
#pragma unroll
        for (int p = 0; p < 4; p++) {
            float4 v = *(const float4*)&X[(size_t)(m0 + lr + p * 32) * F_IN + k0 + lc];
            *(float4*)&As[lr + p * 32][lc] = v;
        }
#pragma unroll
        for (int p = 0; p < 2; p++) {
            float4 v = *(const float4*)&W[(size_t)(n0 + lr + p * 32) * F_IN + k0 + lc];
            *(float4*)&Bs[lr + p * 32][lc] = v;
        }
        __syncthreads();
#pragma unroll
        for (int kk = 0; kk < 32; kk += 8) {
            unsigned ah[2][4], al[2][4];
#pragma unroll
            for (int mt = 0; mt < 2; mt++) {
                int rb = wm * 32 + mt * 16;
                float av[4];
                av[0] = As[rb + grp][kk + tig];
                av[1] = As[rb + grp + 8][kk + tig];
                av[2] = As[rb + grp][kk + tig + 4];
                av[3] = As[rb + grp + 8][kk + tig + 4];
#pragma unroll
                for (int q = 0; q < 4; q++) {
                    unsigned h = tf32_of(av[q]);
                    ah[mt][q] = h;
                    al[mt][q] = tf32_of(av[q] - __uint_as_float(h));
                }
            }
            unsigned bh[4][2], bl[4][2];
#pragma unroll
            for (int nt = 0; nt < 4; nt++) {
                int cb = wn * 32 + nt * 8;
                float bv[2];
                bv[0] = Bs[cb + grp][kk + tig];
                bv[1] = Bs[cb + grp][kk + tig + 4];
#pragma unroll
                for (int q = 0; q < 2; q++) {
                    unsigned h = tf32_of(bv[q]);
                    bh[nt][q] = h;
                    bl[nt][q] = tf32_of(bv[q] - __uint_as_float(h));
                }
            }
#pragma unroll
            for (int mt = 0; mt < 2; mt++)
#pragma unroll
                for (int nt = 0; nt < 4; nt++) {
                    mma_tf32(d[mt][nt], ah[mt], bh[nt]);
                    mma_tf32(d[mt][nt], al[mt], bh[nt]);
                    mma_tf32(d[mt][nt], ah[mt], bl[nt]);
                }
        }
        __syncthreads();
    }
#pragma unroll
    for (int mt = 0; mt < 2; mt++)
#pragma unroll
        for (int nt = 0; nt < 4; nt++) {
            int r = m0 + wm * 32 + mt * 16 + grp;
            int c = n0 + wn * 32 + nt * 8 + tig * 2;
            size_t i00 = (size_t)r * F_OUT + c;
            size_t i10 = (size_t)(r + 8) * F_OUT + c;
            g_S[i00]     = d[mt][nt][0];
            g_S[i00 + 1] = d[mt][nt][1];
            g_S[i10]     = d[mt][nt][2];
            g_S[i10 + 1] = d[mt][nt][3];
            g_St[i00]     = tf32_of(d[mt][nt][0]);
            g_St[i00 + 1] = tf32_of(d[mt][nt][1]);
            g_St[i10]     = tf32_of(d[mt][nt][2]);
            g_St[i10 + 1] = tf32_of(d[mt][nt][3]);
        }
}

// ---------------- K2: f1 = S@f1_w + b1, f2 = S@f2_w + b2 -------------------
__global__ __launch_bounds__(256) void k2_fvec(const float* __restrict__ f1w,
                                               const float* __restrict__ f1b,
                                               const float* __restrict__ f2w,
                                               const float* __restrict__ f2b) {
    int row = blockIdx.x * 8 + (threadIdx.x >> 5);
    int lane = threadIdx.x & 31;
    const float* Sr = g_S + (size_t)row * F_OUT;
    float s1 = 0.f, s2 = 0.f;
    for (int c = lane; c < F_OUT; c += 32) {
        float v = Sr[c];
        s1 = fmaf(v, f1w[c], s1);
        s2 = fmaf(v, f2w[c], s2);
    }
#pragma unroll
    for (int o = 16; o > 0; o >>= 1) {
        s1 += __shfl_xor_sync(0xffffffff, s1, o);
        s2 += __shfl_xor_sync(0xffffffff, s2, o);
    }
    if (lane == 0) {
        g_f1[row] = s1 + f1b[0];
        g_f2[row] = s2 + f2b[0];
    }
}

// ---------------- K3: RWR only (Z now fused into K4) -----------------------
__global__ __launch_bounds__(256) void k3_rwr(const int* __restrict__ adj_ad,
                                              float* __restrict__ out_ri,
                                              int write_ri) {
    const int i = blockIdx.x;
    const int tid = threadIdx.x;
    const int4* crow = (const int4*)(adj_ad + (size_t)i * N_NODES);
    int cnt = 0;
    for (int j4 = tid; j4 < N_NODES / 4; j4 += 256) {
        int4 c = crow[j4];
        cnt += (c.x == 2 || c.x == 3);
        cnt += (c.y == 2 || c.y == 3);
        cnt += (c.z == 2 || c.z == 3);
        cnt += (c.w == 2 || c.w == 3);
    }
    __shared__ int sc[256];
    sc[tid] = cnt;
    __syncthreads();
    for (int s = 128; s > 0; s >>= 1) {
        if (tid < s) sc[tid] += sc[tid + s];
        __syncthreads();
    }
    if (tid == 0 && write_ri) {
        float k = (float)sc[0];
        float den = 1.0f - 0.25f * k;
        float r0, rn;
        if (den == 0.0f) { r0 = 1.0f; rn = 0.5f; }
        else             { r0 = fabsf(1.0f / den); rn = fabsf(0.5f / den); }
        out_ri[2 * i]     = r0;
        out_ri[2 * i + 1] = rn;
    }
}

// ---------------- K4: fused attention GEMM  h = elu(P@S / Z + bias) --------
// 3-stage cp.async pipeline: adj raw tiles + pre-tf32 S tiles prefetched two
// iterations ahead; P generated on the fly (flash-style); Z accumulated
// in-kernel. BM=128 BN=256 BK=32, 8 warps (2M x 4N), warp tile 64x64.
#define APAD 36
#define BPAD 260
#define ADJ_ST (128 * APAD)          // floats per adj stage
#define SS_ST  (32 * BPAD)           // uints per S stage
#define OFF_ADJ  0
#define OFF_SS   (3 * ADJ_ST)
#define OFF_PS   (OFF_SS + 3 * SS_ST)
#define OFF_F1   (OFF_PS + 128 * APAD)
#define OFF_ZR   (OFF_F1 + 128)
#define OFF_RZ   (OFF_ZR + 128)
#define K4_WORDS (OFF_RZ + 128)
#define K4_SMEM  (K4_WORDS * 4)

__device__ __forceinline__ void k4_issue_stage(float* adjS, unsigned* ssS,
                                               const float* __restrict__ adj,
                                               int m0, int n0, int j0, int tid) {
#pragma unroll
    for (int k = 0; k < 4; k++) {
        int c = tid + k * 256;                  // 0..1023
        int row = c >> 3, col = (c & 7) << 2;
        cp16(&adjS[row * APAD + col], &adj[(size_t)(m0 + row) * N_NODES + j0 + col]);
    }
#pragma unroll
    for (int k = 0; k < 8; k++) {
        int c = tid + k * 256;                  // 0..2047
        int row = c >> 6, col = (c & 63) << 2;
        cp16(&ssS[row * BPAD + col], &g_St[(size_t)(j0 + row) * F_OUT + n0 + col]);
    }
}

__global__ __launch_bounds__(256, 1) void k4_attn(const float* __restrict__ adj,
                                                  const float* __restrict__ bias,
                                                  float* __restrict__ out) {
    extern __shared__ float smem[];
    float*    adjA = smem + OFF_ADJ;             // 3 x [128][36]
    unsigned* SsA  = (unsigned*)(smem + OFF_SS); // 3 x [32][260] tf32
    unsigned* Ps   = (unsigned*)(smem + OFF_PS); // [128][36] tf32
    float*    f1s  = smem + OFF_F1;              // [128]
    float*    zrow = smem + OFF_ZR;              // [128]
    float*    rzs  = smem + OFF_RZ;              // [128]

    const int tid = threadIdx.x;
    const int m0 = blockIdx.y * 128;
    const int n0 = blockIdx.x * 256;
    const int warp = tid >> 5, lane = tid & 31;
    const int grp = lane >> 2, tig = lane & 3;
    const int wm = warp >> 2, wn = warp & 3;
    const int gr = tid >> 3;                     // 0..31 row slice for P gen
    const int gc = (tid & 7) << 2;               // col slice for P gen

    if (tid < 128) f1s[tid] = g_f1[m0 + tid];

    float d[4][8][4];
#pragma unroll
    for (int mt = 0; mt < 4; mt++)
#pragma unroll
        for (int nt = 0; nt < 8; nt++)
#pragma unroll
            for (int q = 0; q < 4; q++) d[mt][nt][q] = 0.0f;
    float zacc[4] = {0.f, 0.f, 0.f, 0.f};

    // prologue: prefetch stages 0 and 1
    k4_issue_stage(adjA + 0 * ADJ_ST, SsA + 0 * SS_ST, adj, m0, n0, 0, tid);
    cp_commit();
    k4_issue_stage(adjA + 1 * ADJ_ST, SsA + 1 * SS_ST, adj, m0, n0, 32, tid);
    cp_commit();

    int s = 0;
    for (int it = 0; it < N_NODES / 32; it++) {
        const int j0 = it * 32;
        float* adjS   = adjA + s * ADJ_ST;
        unsigned* SsS = SsA + s * SS_ST;

        cp_wait1();
        __syncthreads();

        // refill stage (s+2)%3 two iterations ahead (its old readers finished
        // before the sync above)
        {
            int s2 = s + 2; if (s2 >= 3) s2 -= 3;
            int jn = j0 + 64;
            if (jn < N_NODES)
                k4_issue_stage(adjA + s2 * ADJ_ST, SsA + s2 * SS_ST, adj, m0, n0, jn, tid);
            cp_commit();
        }

        // --- P-gen: p = exp(leakyrelu(f1_i + f2_j) + adj_ij), Z accumulate ---
        float4 f2v = *(const float4*)&g_f2[j0 + gc];
#pragma unroll
        for (int p = 0; p < 4; p++) {
            int r = gr + p * 32;
            float4 a = *(const float4*)&adjS[r * APAD + gc];
            float f1v = f1s[r];
            float l, e0, e1, e2, e3;
            l = f1v + f2v.x; l = l > 0.f ? l : 0.2f * l; e0 = fast_exp(l + a.x);
            l = f1v + f2v.y; l = l > 0.f ? l : 0.2f * l; e1 = fast_exp(l + a.y);
            l = f1v + f2v.z; l = l > 0.f ? l : 0.2f * l; e2 = fast_exp(l + a.z);
            l = f1v + f2v.w; l = l > 0.f ? l : 0.2f * l; e3 = fast_exp(l + a.w);
            zacc[p] += (e0 + e1) + (e2 + e3);
            uint4 q;
            q.x = tf32_of(e0); q.y = tf32_of(e1); q.z = tf32_of(e2); q.w = tf32_of(e3);
            *(uint4*)&Ps[r * APAD + gc] = q;
        }
        __syncthreads();

        // --- MMA over this K-slab ---
#pragma unroll
        for (int kk = 0; kk < 32; kk += 8) {
            unsigned a[4][4];
#pragma unroll
            for (int mt = 0; mt < 4; mt++) {
                int rb = wm * 64 + mt * 16;
                a[mt][0] = Ps[(rb + grp) * APAD + kk + tig];
                a[mt][1] = Ps[(rb + grp + 8) * APAD + kk + tig];
                a[mt][2] = Ps[(rb + grp) * APAD + kk + tig + 4];
                a[mt][3] = Ps[(rb + grp + 8) * APAD + kk + tig + 4];
            }
            unsigned b[8][2];
#pragma unroll
            for (int nt = 0; nt < 8; nt++) {
                int cb = wn * 64 + nt * 8;
                b[nt][0] = SsS[(kk + tig) * BPAD + cb + grp];
                b[nt][1] = SsS[(kk + tig + 4) * BPAD + cb + grp];
            }
#pragma unroll
            for (int mt = 0; mt < 4; mt++)
#pragma unroll
                for (int nt = 0; nt < 8; nt++)
                    mma_tf32(d[mt][nt], a[mt], b[nt]);
        }
        __syncthreads();   // all reads of Ps + stage s done before reuse

        s++; if (s >= 3) s -= 3;
    }

    // --- Z reduction: 8 threads per row -> zrow ---
#pragma unroll
    for (int m = 1; m < 8; m <<= 1) {
#pragma unroll
        for (int p = 0; p < 4; p++)
            zacc[p] += __shfl_xor_sync(0xffffffff, zacc[p], m);
    }
    if ((tid & 7) == 0) {
#pragma unroll
        for (int p = 0; p < 4; p++) zrow[gr + p * 32] = zacc[p];
    }
    __syncthreads();
    if (tid < 128) rzs[tid] = 1.0f / zrow[tid];
    __syncthreads();

    // --- epilogue: /Z, +bias, ELU ---
#pragma unroll
    for (int mt = 0; mt < 4; mt++) {
        int rl = wm * 64 + mt * 16 + grp;
        float rz0 = rzs[rl], rz1 = rzs[rl + 8];
        int gi = m0 + rl;
#pragma unroll
        for (int nt = 0; nt < 8; nt++) {
            int cl = wn * 64 + nt * 8 + tig * 2;
            int gf = n0 + cl;
            float b0 = bias[gf], b1 = bias[gf + 1];
            float v;
            v = fmaf(d[mt][nt][0], rz0, b0);
            out[(size_t)gi * F_OUT + gf]           = v > 0.f ? v : fast_exp(v) - 1.0f;
            v = fmaf(d[mt][nt][1], rz0, b1);
            out[(size_t)gi * F_OUT + gf + 1]       = v > 0.f ? v : fast_exp(v) - 1.0f;
            v = fmaf(d[mt][nt][2], rz1, b0);
            out[(size_t)(gi + 8) * F_OUT + gf]     = v > 0.f ? v : fast_exp(v) - 1.0f;
            v = fmaf(d[mt][nt][3], rz1, b1);
            out[(size_t)(gi + 8) * F_OUT + gf + 1] = v > 0.f ? v : fast_exp(v) - 1.0f;
        }
    }
}

// ---------------- launch ----------------
extern "C" void kernel_launch(void* const* d_in, const int* in_sizes, int n_in,
                              void* d_out, int out_size) {
    const float* x      = (const float*)d_in[0];
    const float* adj    = (const float*)d_in[1];
    const int*   adj_ad = (const int*)d_in[2];
    const float* seq_W  = (const float*)d_in[3];
    const float* f1w    = (const float*)d_in[4];
    const float* f1b    = (const float*)d_in[5];
    const float* f2w    = (const float*)d_in[6];
    const float* f2b    = (const float*)d_in[7];
    const float* bias   = (const float*)d_in[8];
    float* out = (float*)d_out;

    static int smem_set = 0;
    if (!smem_set) {
        cudaFuncSetAttribute(k4_attn, cudaFuncAttributeMaxDynamicSharedMemorySize, K4_SMEM);
        smem_set = 1;
    }

    k1_seqfts<<<dim3(8, 64), 256>>>(x, seq_W);
    k2_fvec<<<N_NODES / 8, 256>>>(f1w, f1b, f2w, f2b);
    int write_ri = (out_size >= N_NODES * F_OUT + 2 * N_NODES) ? 1 : 0;
    k3_rwr<<<N_NODES, 256>>>(adj_ad, out + (size_t)N_NODES * F_OUT, write_ri);
    k4_attn<<<dim3(2, 64), 256, K4_SMEM>>>(adj, bias, out);
}

// round 4
// speedup vs baseline: 1.3802x; 1.1507x over previous
#include <cuda_runtime.h>
#include <cstdint>

#define N_NODES 8192
#define F_IN    1024
#define F_OUT   512

// ---------------- device scratch ----------------
__device__ float    g_S [N_NODES * F_OUT];   // seq_fts fp32 (16 MB)
__device__ unsigned g_St[N_NODES * F_OUT];   // seq_fts tf32 bits (16 MB)
__device__ float    g_f1[N_NODES];
__device__ float    g_f2[N_NODES];

// ---------------- helpers ----------------
__device__ __forceinline__ float fast_exp(float x) {
    float t = x * 1.4426950408889634f;
    t = fminf(fmaxf(t, -126.0f), 126.0f);
    float fi = rintf(t);
    float f  = t - fi;
    float p  =          1.5403530393381609e-4f;
    p = fmaf(p, f, 1.3333558146428443e-3f);
    p = fmaf(p, f, 9.6181291076284772e-3f);
    p = fmaf(p, f, 5.5504108664821580e-2f);
    p = fmaf(p, f, 2.4022650695910071e-1f);
    p = fmaf(p, f, 6.9314718055994531e-1f);
    p = fmaf(p, f, 1.0f);
    int e = (int)fi;
    return p * __int_as_float((e + 127) << 23);
}

__device__ __forceinline__ unsigned tf32_of(float x) {
    unsigned r;
    asm("cvt.rna.tf32.f32 %0, %1;" : "=r"(r) : "f"(x));
    return r;
}

__device__ __forceinline__ void mma_tf32(float* d, const unsigned* a, const unsigned* b) {
    asm volatile(
        "mma.sync.aligned.m16n8k8.row.col.f32.tf32.tf32.f32 "
        "{%0,%1,%2,%3}, {%4,%5,%6,%7}, {%8,%9}, {%0,%1,%2,%3};"
        : "+f"(d[0]), "+f"(d[1]), "+f"(d[2]), "+f"(d[3])
        : "r"(a[0]), "r"(a[1]), "r"(a[2]), "r"(a[3]), "r"(b[0]), "r"(b[1]));
}

__device__ __forceinline__ void cp16(void* smem_ptr, const void* gptr) {
    unsigned sa = (unsigned)__cvta_generic_to_shared(smem_ptr);
    asm volatile("cp.async.cg.shared.global [%0], [%1], 16;" :: "r"(sa), "l"(gptr));
}
__device__ __forceinline__ void cp_commit() { asm volatile("cp.async.commit_group;"); }
__device__ __forceinline__ void cp_wait1()  { asm volatile("cp.async.wait_group 1;"); }

// ---------------- K1: seq_fts = x @ seq_W.T (single tf32) ------------------
__global__ __launch_bounds__(256) void k1_seqfts(const float* __restrict__ X,
                                                 const float* __restrict__ W) {
    __shared__ float As[128][36];
    __shared__ float Bs[64][36];
    const int tid = threadIdx.x;
    const int m0 = blockIdx.y * 128;
    const int n0 = blockIdx.x * 64;
    const int warp = tid >> 5, lane = tid & 31;
    const int grp = lane >> 2, tig = lane & 3;
    const int wm = warp & 3, wn = warp >> 2;
    const int lr = tid >> 3;
    const int lc = (tid & 7) << 2;

    float d[2][4][4];
#pragma unroll
    for (int i = 0; i < 2; i++)
#pragma unroll
        for (int j = 0; j < 4; j++)
#pragma unroll
            for (int q = 0; q < 4; q++) d[i][j][q] = 0.0f;

    for (int k0 = 0; k0 < F_IN; k0 += 32) {
#pragma unroll
        for (int p = 0; p < 4; p++) {
            float4 v = *(const float4*)&X[(size_t)(m0 + lr + p * 32) * F_IN + k0 + lc];
            *(float4*)&As[lr + p * 32][lc] = v;
        }
#pragma unroll
        for (int p = 0; p < 2; p++) {
            float4 v = *(const float4*)&W[(size_t)(n0 + lr + p * 32) * F_IN + k0 + lc];
            *(float4*)&Bs[lr + p * 32][lc] = v;
        }
        __syncthreads();
#pragma unroll
        for (int kk = 0; kk < 32; kk += 8) {
            unsigned ah[2][4];
#pragma unroll
            for (int mt = 0; mt < 2; mt++) {
                int rb = wm * 32 + mt * 16;
                ah[mt][0] = tf32_of(As[rb + grp][kk + tig]);
                ah[mt][1] = tf32_of(As[rb + grp + 8][kk + tig]);
                ah[mt][2] = tf32_of(As[rb + grp][kk + tig + 4]);
                ah[mt][3] = tf32_of(As[rb + grp + 8][kk + tig + 4]);
            }
            unsigned bh[4][2];
#pragma unroll
            for (int nt = 0; nt < 4; nt++) {
                int cb = wn * 32 + nt * 8;
                bh[nt][0] = tf32_of(Bs[cb + grp][kk + tig]);
                bh[nt][1] = tf32_of(Bs[cb + grp][kk + tig + 4]);
            }
#pragma unroll
            for (int mt = 0; mt < 2; mt++)
#pragma unroll
                for (int nt = 0; nt < 4; nt++)
                    mma_tf32(d[mt][nt], ah[mt], bh[nt]);
        }
        __syncthreads();
    }
#pragma unroll
    for (int mt = 0; mt < 2; mt++)
#pragma unroll
        for (int nt = 0; nt < 4; nt++) {
            int r = m0 + wm * 32 + mt * 16 + grp;
            int c = n0 + wn * 32 + nt * 8 + tig * 2;
            size_t i00 = (size_t)r * F_OUT + c;
            size_t i10 = (size_t)(r + 8) * F_OUT + c;
            g_S[i00]     = d[mt][nt][0];
            g_S[i00 + 1] = d[mt][nt][1];
            g_S[i10]     = d[mt][nt][2];
            g_S[i10 + 1] = d[mt][nt][3];
            g_St[i00]     = tf32_of(d[mt][nt][0]);
            g_St[i00 + 1] = tf32_of(d[mt][nt][1]);
            g_St[i10]     = tf32_of(d[mt][nt][2]);
            g_St[i10 + 1] = tf32_of(d[mt][nt][3]);
        }
}

// ---------------- K2: f1/f2 projections -------------------------------------
__global__ __launch_bounds__(256) void k2_fvec(const float* __restrict__ f1w,
                                               const float* __restrict__ f1b,
                                               const float* __restrict__ f2w,
                                               const float* __restrict__ f2b) {
    int row = blockIdx.x * 8 + (threadIdx.x >> 5);
    int lane = threadIdx.x & 31;
    const float* Sr = g_S + (size_t)row * F_OUT;
    float s1 = 0.f, s2 = 0.f;
    for (int c = lane; c < F_OUT; c += 32) {
        float v = Sr[c];
        s1 = fmaf(v, f1w[c], s1);
        s2 = fmaf(v, f2w[c], s2);
    }
#pragma unroll
    for (int o = 16; o > 0; o >>= 1) {
        s1 += __shfl_xor_sync(0xffffffff, s1, o);
        s2 += __shfl_xor_sync(0xffffffff, s2, o);
    }
    if (lane == 0) {
        g_f1[row] = s1 + f1b[0];
        g_f2[row] = s2 + f2b[0];
    }
}

// ---------------- K3: RWR ----------------------------------------------------
__global__ __launch_bounds__(256) void k3_rwr(const int* __restrict__ adj_ad,
                                              float* __restrict__ out_ri,
                                              int write_ri) {
    const int i = blockIdx.x;
    const int tid = threadIdx.x;
    const int4* crow = (const int4*)(adj_ad + (size_t)i * N_NODES);
    int cnt = 0;
    for (int j4 = tid; j4 < N_NODES / 4; j4 += 256) {
        int4 c = crow[j4];
        cnt += (c.x == 2 || c.x == 3);
        cnt += (c.y == 2 || c.y == 3);
        cnt += (c.z == 2 || c.z == 3);
        cnt += (c.w == 2 || c.w == 3);
    }
    __shared__ int sc[256];
    sc[tid] = cnt;
    __syncthreads();
    for (int s = 128; s > 0; s >>= 1) {
        if (tid < s) sc[tid] += sc[tid + s];
        __syncthreads();
    }
    if (tid == 0 && write_ri) {
        float k = (float)sc[0];
        float den = 1.0f - 0.25f * k;
        float r0, rn;
        if (den == 0.0f) { r0 = 1.0f; rn = 0.5f; }
        else             { r0 = fabsf(1.0f / den); rn = fabsf(0.5f / den); }
        out_ri[2 * i]     = r0;
        out_ri[2 * i + 1] = rn;
    }
}

// ---------------- K4: fused attention GEMM  h = elu(P@S / Z + bias) --------
// Single-phase pipeline: at slab s each warp interleaves P-gen(s+1) (FMA pipe)
// with MMA(s) (tensor pipe). P double-buffered, B quad-buffered, adj triple-
// buffered via cp.async. ONE __syncthreads per slab.
#define BPAD   260
#define BST    (32 * BPAD)            // words per B stage (33280 B)
#define PST    (128 * 36)             // words per P stage (18432 B)
#define AST    (128 * 36)             // words per adj stage
#define OFFB   0
#define OFFP   (OFFB + 4 * BST)
#define OFFA   (OFFP + 2 * PST)
#define OFFM   (OFFA + 3 * AST)
#define K4_SMEM ((OFFM + 640) * 4)

__device__ __forceinline__ void k4_issue(float* sm, const float* __restrict__ adj,
                                         int m0, int n0, int s, int tid) {
    float*    Bb = sm + OFFB + (s & 3) * BST;
    float*    Ab = sm + OFFA + (s % 3) * AST;
    const int j0 = s * 32;
#pragma unroll
    for (int k = 0; k < 8; k++) {                 // B: 32 rows x 256 cols (tf32)
        int idx = tid + k * 256;
        int r = idx >> 6, c = (idx & 63) << 2;
        cp16(&Bb[r * BPAD + c], &g_St[(size_t)(j0 + r) * F_OUT + n0 + c]);
    }
#pragma unroll
    for (int k = 0; k < 4; k++) {                 // adj: 128 rows x 32 cols
        int idx = tid + k * 256;
        int r = idx >> 3, c = (idx & 7) << 2;
        cp16(&Ab[r * 36 + c], &adj[(size_t)(m0 + r) * N_NODES + j0 + c]);
    }
}

// one quarter of a P tile: 4 exps for row r = gr + kk8*32, cols gc..gc+3
__device__ __forceinline__ void pgen_chunk(const float* adjS, unsigned* Pn,
                                           const float* f1s, const float4& f2v,
                                           int gr, int gc, int kk8, float* zacc) {
    int r = gr + kk8 * 32;
    float4 a = *(const float4*)&adjS[r * 36 + gc];
    float f1v = f1s[r];
    float l, e0, e1, e2, e3;
    l = f1v + f2v.x; l = l > 0.f ? l : 0.2f * l; e0 = fast_exp(l + a.x);
    l = f1v + f2v.y; l = l > 0.f ? l : 0.2f * l; e1 = fast_exp(l + a.y);
    l = f1v + f2v.z; l = l > 0.f ? l : 0.2f * l; e2 = fast_exp(l + a.z);
    l = f1v + f2v.w; l = l > 0.f ? l : 0.2f * l; e3 = fast_exp(l + a.w);
    zacc[kk8] += (e0 + e1) + (e2 + e3);
    uint4 q;
    q.x = tf32_of(e0); q.y = tf32_of(e1); q.z = tf32_of(e2); q.w = tf32_of(e3);
    *(uint4*)&Pn[r * 36 + gc] = q;
}

__global__ __launch_bounds__(256, 1) void k4_attn(const float* __restrict__ adj,
                                                  const float* __restrict__ bias,
                                                  float* __restrict__ out) {
    extern __shared__ float sm[];
    float* f1s   = sm + OFFM;          // 128
    float* zrow  = sm + OFFM + 128;    // 128
    float* rzs   = sm + OFFM + 256;    // 128
    float* sbias = sm + OFFM + 384;    // 256

    const int tid = threadIdx.x;
    const int m0 = blockIdx.y * 128;
    const int n0 = blockIdx.x * 256;
    const int warp = tid >> 5, lane = tid & 31;
    const int grp = lane >> 2, tig = lane & 3;
    const int wm = warp >> 2, wn = warp & 3;
    const int gr = tid >> 3;                 // 0..31
    const int gc = (tid & 7) << 2;           // 0..28

    if (tid < 128) f1s[tid] = g_f1[m0 + tid];
    sbias[tid] = bias[n0 + tid];

    float d[4][8][4];
#pragma unroll
    for (int mt = 0; mt < 4; mt++)
#pragma unroll
        for (int nt = 0; nt < 8; nt++)
#pragma unroll
            for (int q = 0; q < 4; q++) d[mt][nt][q] = 0.0f;
    float zacc[4] = {0.f, 0.f, 0.f, 0.f};

    // prologue: stage slabs 0,1; P-gen slab 0
    k4_issue(sm, adj, m0, n0, 0, tid); cp_commit();
    k4_issue(sm, adj, m0, n0, 1, tid); cp_commit();
    cp_wait1();                 // slab 0 loads done
    __syncthreads();
    {
        const float* adjS = sm + OFFA;                 // stage 0
        unsigned* Pn = (unsigned*)(sm + OFFP);         // P buffer 0
        float4 f2v = *(const float4*)&g_f2[gc];
#pragma unroll
        for (int kk8 = 0; kk8 < 4; kk8++)
            pgen_chunk(adjS, Pn, f1s, f2v, gr, gc, kk8, zacc);
    }

    for (int s = 0; s < 256; s++) {
        if (s + 2 < 256) k4_issue(sm, adj, m0, n0, s + 2, tid);
        cp_commit();
        cp_wait1();             // slab s+1 loads done
        __syncthreads();        // publish adj(s+1)/B(s+1); P[(s+1)&1] now free

        const unsigned* Pc = (const unsigned*)(sm + OFFP + (s & 1) * PST);
        const unsigned* Bc = (const unsigned*)(sm + OFFB + (s & 3) * BST);
        const float*  adjS1 = sm + OFFA + ((s + 1) % 3) * AST;
        unsigned*        Pn = (unsigned*)(sm + OFFP + ((s + 1) & 1) * PST);
        const bool gen = (s + 1 < 256);
        float4 f2v;
        if (gen) f2v = *(const float4*)&g_f2[(s + 1) * 32 + gc];

#pragma unroll
        for (int kk8 = 0; kk8 < 4; kk8++) {
            // P-gen for slab s+1 (FMA pipe) — interleaves with MMAs below
            if (gen) pgen_chunk(adjS1, Pn, f1s, f2v, gr, gc, kk8, zacc);

            const int kk = kk8 * 8;
            unsigned a[4][4];
#pragma unroll
            for (int mt = 0; mt < 4; mt++) {
                int rb = wm * 64 + mt * 16;
                a[mt][0] = Pc[(rb + grp) * 36 + kk + tig];
                a[mt][1] = Pc[(rb + grp + 8) * 36 + kk + tig];
                a[mt][2] = Pc[(rb + grp) * 36 + kk + tig + 4];
                a[mt][3] = Pc[(rb + grp + 8) * 36 + kk + tig + 4];
            }
            unsigned b[8][2];
#pragma unroll
            for (int nt = 0; nt < 8; nt++) {
                int cb = wn * 64 + nt * 8;
                b[nt][0] = Bc[(kk + tig) * BPAD + cb + grp];
                b[nt][1] = Bc[(kk + tig + 4) * BPAD + cb + grp];
            }
#pragma unroll
            for (int mt = 0; mt < 4; mt++)
#pragma unroll
                for (int nt = 0; nt < 8; nt++)
                    mma_tf32(d[mt][nt], a[mt], b[nt]);
        }
    }

    // ---- Z reduction (8 threads per row) ----
#pragma unroll
    for (int m = 1; m < 8; m <<= 1)
#pragma unroll
        for (int p = 0; p < 4; p++)
            zacc[p] += __shfl_xor_sync(0xffffffff, zacc[p], m);
    if ((tid & 7) == 0) {
#pragma unroll
        for (int p = 0; p < 4; p++) zrow[gr + p * 32] = zacc[p];
    }
    __syncthreads();
    if (tid < 128) rzs[tid] = 1.0f / zrow[tid];
    __syncthreads();

    // ---- epilogue: /Z, +bias, ELU ----
#pragma unroll
    for (int mt = 0; mt < 4; mt++) {
        int rl = wm * 64 + mt * 16 + grp;
        float rz0 = rzs[rl], rz1 = rzs[rl + 8];
        int gi = m0 + rl;
#pragma unroll
        for (int nt = 0; nt < 8; nt++) {
            int cl = wn * 64 + nt * 8 + tig * 2;
            int gf = n0 + cl;
            float b0 = sbias[cl], b1 = sbias[cl + 1];
            float v;
            v = fmaf(d[mt][nt][0], rz0, b0);
            out[(size_t)gi * F_OUT + gf]           = v > 0.f ? v : fast_exp(v) - 1.0f;
            v = fmaf(d[mt][nt][1], rz0, b1);
            out[(size_t)gi * F_OUT + gf + 1]       = v > 0.f ? v : fast_exp(v) - 1.0f;
            v = fmaf(d[mt][nt][2], rz1, b0);
            out[(size_t)(gi + 8) * F_OUT + gf]     = v > 0.f ? v : fast_exp(v) - 1.0f;
            v = fmaf(d[mt][nt][3], rz1, b1);
            out[(size_t)(gi + 8) * F_OUT + gf + 1] = v > 0.f ? v : fast_exp(v) - 1.0f;
        }
    }
}

// ---------------- launch ----------------
extern "C" void kernel_launch(void* const* d_in, const int* in_sizes, int n_in,
                              void* d_out, int out_size) {
    const float* x      = (const float*)d_in[0];
    const float* adj    = (const float*)d_in[1];
    const int*   adj_ad = (const int*)d_in[2];
    const float* seq_W  = (const float*)d_in[3];
    const float* f1w    = (const float*)d_in[4];
    const float* f1b    = (const float*)d_in[5];
    const float* f2w    = (const float*)d_in[6];
    const float* f2b    = (const float*)d_in[7];
    const float* bias   = (const float*)d_in[8];
    float* out = (float*)d_out;

    static int smem_set = 0;
    if (!smem_set) {
        cudaFuncSetAttribute(k4_attn, cudaFuncAttributeMaxDynamicSharedMemorySize, K4_SMEM);
        smem_set = 1;
    }

    k1_seqfts<<<dim3(8, 64), 256>>>(x, seq_W);
    k2_fvec<<<N_NODES / 8, 256>>>(f1w, f1b, f2w, f2b);
    int write_ri = (out_size >= N_NODES * F_OUT + 2 * N_NODES) ? 1 : 0;
    k3_rwr<<<N_NODES, 256>>>(adj_ad, out + (size_t)N_NODES * F_OUT, write_ri);
    k4_attn<<<dim3(2, 64), 256, K4_SMEM>>>(adj, bias, out);
}